// round 7
// baseline (speedup 1.0000x reference)
#include <cuda_runtime.h>
#include <math.h>
#include <stdint.h>

#define NROW 4096
#define CH   1024
#define MQ   8
#define KQ   2048
#define DQ   128
#define CAP  64

// Per-(level,m) max_k |c_k|^2, as ordered uint (floats >= 0). Zero-initialized at
// module load; atomicMax over a fixed input set is idempotent across graph replays.
static __device__ unsigned g_cm2[2][MQ];

// One warp per 4 consecutive k: 4 interleaved butterflies, one atomicMax.
__global__ void cm2_k(const float* __restrict__ cb0, const float* __restrict__ cb1) {
    const int level = blockIdx.y;
    const float* cb = level ? cb1 : cb0;
    const int w    = (blockIdx.x * blockDim.x + threadIdx.x) >> 5;
    const int lane = threadIdx.x & 31;
    if (w >= (MQ * KQ) / 4) return;
    float s[4];
#pragma unroll
    for (int r = 0; r < 4; r++) {
        float4 v = reinterpret_cast<const float4*>(cb)[(size_t)(w * 4 + r) * (DQ / 4) + lane];
        s[r] = v.x * v.x + v.y * v.y + v.z * v.z + v.w * v.w;
    }
#pragma unroll
    for (int o = 16; o; o >>= 1)
#pragma unroll
        for (int r = 0; r < 4; r++) s[r] += __shfl_xor_sync(0xffffffffu, s[r], o);
    if (lane == 0) {
        float mx = fmaxf(fmaxf(s[0], s[1]), fmaxf(s[2], s[3]));
        atomicMax(&g_cm2[level][(w * 4) >> 11], __float_as_uint(mx));
    }
}

__device__ __forceinline__ float warp_sum(float v) {
#pragma unroll
    for (int o = 16; o; o >>= 1) v += __shfl_xor_sync(0xffffffffu, v, o);
    return v;
}
// Max of non-negative floats: bit pattern is order-isomorphic to uint.
__device__ __forceinline__ float warp_max_pos(float v) {
    unsigned r;
    asm("redux.sync.max.u32 %0, %1, 0xffffffff;" : "=r"(r) : "r"(__float_as_uint(v)));
    return __uint_as_float(r);
}

// One warp, one (n,m) row, one level. Single streaming pass: running max +
// speculative pushes (u >= UTHR0) into smem; then exact filter with the true
// threshold (or rare L2-hit fallback rescan). No register cache of u.
__device__ __forceinline__ int pick_code(
    float4 z, float x2, float t,
    const float* __restrict__ cbm,
    float cm2,
    const float4* __restrict__ u4row,
    int lane, int* s_cnt,            // 2 counters
    int* kl1, float* ul1,            // speculative list
    int* kl2, float* ul2)            // final candidate list
{
    const float UTHR0 = 0.995f;
    if (lane == 0) { s_cnt[0] = 0; s_cnt[1] = 0; }
    __syncwarp();

    // Pass 1: front-batched burst of 16 LDG.128/lane; running max; speculative
    // pushes (group-max test rarely true -> branch almost never taken).
    float umax = 0.0f;
#pragma unroll
    for (int j = 0; j < 16; j++) {
        const float4 v = u4row[j * 32 + lane];
        const float vm = fmaxf(fmaxf(v.x, v.y), fmaxf(v.z, v.w));
        umax = fmaxf(umax, vm);
        if (vm >= UTHR0) {
            const int kb = (j * 32 + lane) * 4;
            if (v.x >= UTHR0) { int q = atomicAdd(&s_cnt[0], 1); if (q < CAP) { kl1[q] = kb + 0; ul1[q] = v.x; } }
            if (v.y >= UTHR0) { int q = atomicAdd(&s_cnt[0], 1); if (q < CAP) { kl1[q] = kb + 1; ul1[q] = v.y; } }
            if (v.z >= UTHR0) { int q = atomicAdd(&s_cnt[0], 1); if (q < CAP) { kl1[q] = kb + 2; ul1[q] = v.z; } }
            if (v.w >= UTHR0) { int q = atomicAdd(&s_cnt[0], 1); if (q < CAP) { kl1[q] = kb + 3; ul1[q] = v.w; } }
        }
    }
    umax = warp_max_pos(umax);

    const float SCALE = 45.25483399593904f;   // sqrt(2048)
    const float EPSF  = 1e-6f;
    const float HI    = (float)(1.0 - 1e-6);

    // Rigorous spread bound of logit over k (Cauchy-Schwarz), inflated for fp noise.
    const float cmax = sqrtf(cm2);
    float delta = (t / SCALE) * (4.0f * sqrtf(x2) * cmax + cm2);
    delta = delta * 1.01f + 0.02f;

    // g(u) = -log(-log u) monotone in u: candidate iff u >= uthr.
    float ucm  = fminf(fmaxf(umax, EPSF), HI);
    float gm   = -logf(-logf(ucm));
    float uthr = expf(-expf(-(gm - delta))) * (1.0f - 1e-5f);
    uthr = fminf(uthr, umax);     // guarantees the max element qualifies

    __syncwarp();
    const int cntraw = s_cnt[0];

    if (uthr >= UTHR0 && cntraw <= CAP) {
        // Common path (~99%): true candidates are a subset of the speculative
        // list. Lane-parallel exact filter.
        for (int i = lane; i < cntraw; i += 32) {
            const float uv = ul1[i];
            if (uv >= uthr) { int q = atomicAdd(&s_cnt[1], 1); kl2[q] = kl1[i]; ul2[q] = uv; }
        }
    } else {
        // Rare fallback: rescan the just-streamed row (L2-resident) with uthr.
#pragma unroll
        for (int j = 0; j < 16; j++) {
            const float4 v = u4row[j * 32 + lane];
            const float vm = fmaxf(fmaxf(v.x, v.y), fmaxf(v.z, v.w));
            if (vm >= uthr) {
                const int kb = (j * 32 + lane) * 4;
                if (v.x >= uthr) { int q = atomicAdd(&s_cnt[1], 1); if (q < CAP) { kl2[q] = kb + 0; ul2[q] = v.x; } }
                if (v.y >= uthr) { int q = atomicAdd(&s_cnt[1], 1); if (q < CAP) { kl2[q] = kb + 1; ul2[q] = v.y; } }
                if (v.z >= uthr) { int q = atomicAdd(&s_cnt[1], 1); if (q < CAP) { kl2[q] = kb + 2; ul2[q] = v.z; } }
                if (v.w >= uthr) { int q = atomicAdd(&s_cnt[1], 1); if (q < CAP) { kl2[q] = kb + 3; ul2[q] = v.w; } }
            }
        }
    }
    __syncwarp();
    int cnt = s_cnt[1];
    if (cnt > CAP) cnt = CAP;              // statistically unreachable
    if (cnt <= 1) return kl2[0];           // max element always qualifies -> cnt >= 1

    // Fast scoring: dist = sum_d (z_d - c_d)^2 -> ONE butterfly per candidate,
    // 2-wide ILP. Reassociation noise vs the faithful formula is covered by the
    // 1e-2 refinement margin below.
    float best_s = -3.4e38f, sec_s = -3.4e38f;
    int   best_k = 0;
    for (int base = 0; base < cnt; base += 2) {
        float dd[2]; int kk[2];
#pragma unroll
        for (int i2 = 0; i2 < 2; i2++) {
            int i = base + i2; if (i > cnt - 1) i = cnt - 1;
            int k = kl2[i]; kk[i2] = k;
            float4 c = reinterpret_cast<const float4*>(cbm)[(size_t)k * (DQ / 4) + lane];
            float ex = z.x - c.x, ey = z.y - c.y, ez = z.z - c.z, ew = z.w - c.w;
            dd[i2] = ex * ex + ey * ey + ez * ez + ew * ew;
        }
#pragma unroll
        for (int o = 16; o; o >>= 1) {
            dd[0] += __shfl_xor_sync(0xffffffffu, dd[0], o);
            dd[1] += __shfl_xor_sync(0xffffffffu, dd[1], o);
        }
#pragma unroll
        for (int i2 = 0; i2 < 2; i2++) {
            int i = base + i2; if (i >= cnt) break;
            float uc = fminf(fmaxf(ul2[i], EPSF), HI);
            float g  = -logf(-logf(uc));
            float sc = -dd[i2] / SCALE * t + g;
            int   k  = kk[i2];
            if (sc > best_s || (sc == best_s && k < best_k)) {
                sec_s = best_s; best_s = sc; best_k = k;
            } else if (sc > sec_s) sec_s = sc;
        }
    }

    // Refinement (rare, ~1e-2 of rows): reference-faithful fp32 formula with
    // fp64 gumbel. Margin 1e-2 >> combined fp noise of both paths (<~3e-4).
    if (best_s - sec_s < 1e-2f) {
        best_s = -3.4e38f; best_k = 0;
        for (int i = 0; i < cnt; i++) {
            const int k = kl2[i];
            float4 c = reinterpret_cast<const float4*>(cbm)[(size_t)k * (DQ / 4) + lane];
            float p = warp_sum(z.x * c.x + z.y * c.y + z.z * c.z + z.w * c.w);
            float q = warp_sum(c.x * c.x + c.y * c.y + c.z * c.z + c.w * c.w);
            double ucl = (double)fminf(fmaxf(ul2[i], EPSF), HI);
            float  g   = (float)(-log(-log(ucl)));
            float dist  = __fadd_rn(__fadd_rn(x2, q), -__fmul_rn(2.0f, p));
            float logit = __fmul_rn(__fdiv_rn(-dist, SCALE), t);
            float sc    = __fadd_rn(logit, g);
            if (sc > best_s || (sc == best_s && k < best_k)) { best_s = sc; best_k = k; }
        }
    }
    __syncwarp();
    return best_k;
}

__global__ void __launch_bounds__(256) umgm_kernel(
    const float* __restrict__ x,
    const float* __restrict__ cb0,
    const float* __restrict__ cb1,
    const float* __restrict__ t0p,
    const float* __restrict__ t1p,
    const float* __restrict__ u0,
    const float* __restrict__ u1,
    float* __restrict__ out)
{
    __shared__ int   s_cnt[8][2];
    __shared__ int   s_k1[8][CAP];
    __shared__ float s_u1[8][CAP];
    __shared__ int   s_k2[8][CAP];
    __shared__ float s_u2[8][CAP];
    const int w    = threadIdx.x >> 5;
    const int lane = threadIdx.x & 31;
    const int row  = blockIdx.x * 8 + w;   // row = n*M + m (matches u layout)
    const int n    = row >> 3;
    const int m    = row & 7;
    const float EPSF = 1e-6f;

    float4 z = reinterpret_cast<const float4*>(x + (size_t)n * CH + m * DQ)[lane];
    float x2 = warp_sum(z.x * z.x + z.y * z.y + z.z * z.z + z.w * z.w);

    const float* cbm0 = cb0 + (size_t)m * KQ * DQ;
    const float* cbm1 = cb1 + (size_t)m * KQ * DQ;

    // ---- level 0 ----
    int k0 = pick_code(z, x2, fmaxf(t0p[m], EPSF), cbm0,
                       __uint_as_float(g_cm2[0][m]),
                       reinterpret_cast<const float4*>(u0) + (size_t)row * (KQ / 4),
                       lane, s_cnt[w], s_k1[w], s_u1[w], s_k2[w], s_u2[w]);
    float4 c0 = reinterpret_cast<const float4*>(cbm0)[(size_t)k0 * (DQ / 4) + lane];

    float4 z1 = make_float4(z.x - c0.x, z.y - c0.y, z.z - c0.z, z.w - c0.w);
    float x2b = warp_sum(z1.x * z1.x + z1.y * z1.y + z1.z * z1.z + z1.w * z1.w);

    // ---- level 1 ----
    int k1 = pick_code(z1, x2b, fmaxf(t1p[m], EPSF), cbm1,
                       __uint_as_float(g_cm2[1][m]),
                       reinterpret_cast<const float4*>(u1) + (size_t)row * (KQ / 4),
                       lane, s_cnt[w], s_k1[w], s_u1[w], s_k2[w], s_u2[w]);
    float4 c1 = reinterpret_cast<const float4*>(cbm1)[(size_t)k1 * (DQ / 4) + lane];

    float4 o = make_float4(c0.x + c1.x, c0.y + c1.y, c0.z + c1.z, c0.w + c1.w);
    reinterpret_cast<float4*>(out + (size_t)n * CH + m * DQ)[lane] = o;
}

extern "C" void kernel_launch(void* const* d_in, const int* in_sizes, int n_in,
                              void* d_out, int out_size) {
    const float *x = nullptr, *cb0 = nullptr, *cb1 = nullptr,
                *t0 = nullptr, *t1 = nullptr, *u0 = nullptr, *u1 = nullptr;
    for (int i = 0; i < n_in; i++) {
        const float* p = (const float*)d_in[i];
        const long sz = in_sizes[i];
        if      (sz == (long)NROW * CH)        { x = p; }
        else if (sz == (long)MQ * KQ * DQ)     { if (!cb0) cb0 = p; else cb1 = p; }
        else if (sz == (long)MQ)               { if (!t0)  t0  = p; else t1  = p; }
        else if (sz == (long)NROW * MQ * KQ)   { if (!u0)  u0  = p; else u1  = p; }
    }
    float* out = (float*)d_out;
    (void)out_size;

    dim3 gc((MQ * KQ) / (4 * 8), 2);       // warp handles 4 k's, 8 warps/block
    cm2_k<<<gc, 256>>>(cb0, cb1);
    umgm_kernel<<<(NROW * MQ) / 8, 256>>>(x, cb0, cb1, t0, t1, u0, u1, out);
}

// round 9
// speedup vs baseline: 1.6679x; 1.6679x over previous
#include <cuda_runtime.h>
#include <math.h>
#include <stdint.h>

#define NROW 4096
#define CH   1024
#define MQ   8
#define KQ   2048
#define DQ   128
#define CAP  64

// Per-(level,m) max_k |c_k|^2, as ordered uint (floats >= 0). Zero-initialized at
// module load; atomicMax over a fixed input set is idempotent across graph replays.
static __device__ unsigned g_cm2[2][MQ];

// One warp per 4 consecutive k: 4 interleaved butterflies, one atomicMax.
__global__ void cm2_k(const float* __restrict__ cb0, const float* __restrict__ cb1) {
    const int level = blockIdx.y;
    const float* cb = level ? cb1 : cb0;
    const int w    = (blockIdx.x * blockDim.x + threadIdx.x) >> 5;
    const int lane = threadIdx.x & 31;
    if (w >= (MQ * KQ) / 4) return;
    float s[4];
#pragma unroll
    for (int r = 0; r < 4; r++) {
        float4 v = reinterpret_cast<const float4*>(cb)[(size_t)(w * 4 + r) * (DQ / 4) + lane];
        s[r] = v.x * v.x + v.y * v.y + v.z * v.z + v.w * v.w;
    }
#pragma unroll
    for (int o = 16; o; o >>= 1)
#pragma unroll
        for (int r = 0; r < 4; r++) s[r] += __shfl_xor_sync(0xffffffffu, s[r], o);
    if (lane == 0) {
        float mx = fmaxf(fmaxf(s[0], s[1]), fmaxf(s[2], s[3]));
        atomicMax(&g_cm2[level][(w * 4) >> 11], __float_as_uint(mx));
    }
}

__device__ __forceinline__ float warp_sum(float v) {
#pragma unroll
    for (int o = 16; o; o >>= 1) v += __shfl_xor_sync(0xffffffffu, v, o);
    return v;
}
// Max of non-negative floats: bit pattern is order-isomorphic to uint.
__device__ __forceinline__ float warp_max_pos(float v) {
    unsigned r;
    asm("redux.sync.max.u32 %0, %1, 0xffffffff;" : "=r"(r) : "r"(__float_as_uint(v)));
    return __uint_as_float(r);
}

__constant__ float c_SCALE = 45.25483399593904f;   // sqrt(2048)

// Threshold from umax: g(u) = -log(-log u) monotone in u; candidate iff u >= uthr.
// delta = rigorous Cauchy-Schwarz spread bound of the logit, inflated for fp noise.
__device__ __forceinline__ float make_uthr(float umax, float t, float x2, float cm2) {
    const float EPSF = 1e-6f, HI = (float)(1.0 - 1e-6);
    const float cmax = sqrtf(cm2);
    float delta = (t / c_SCALE) * (4.0f * sqrtf(x2) * cmax + cm2);
    delta = delta * 1.01f + 0.02f;
    float ucm  = fminf(fmaxf(umax, EPSF), HI);
    float gm   = -logf(-logf(ucm));
    float uthr = expf(-expf(-(gm - delta))) * (1.0f - 1e-5f);
    return fminf(uthr, umax);                 // guarantees the max element qualifies
}

// Pass 2: branch-free 64-bit candidate mask from register-resident ur, ONE
// ballot, rare divergent pushes into the per-warp smem list. Returns count.
__device__ __forceinline__ int build_push(
    const float4* ur, float uthr, int lane, int* s_cnt, int* kl, float* ul)
{
    if (lane == 0) *s_cnt = 0;
    unsigned m0 = 0u, m1 = 0u;
#pragma unroll
    for (int j = 0; j < 16; j++) {
        const float4 v = ur[j];
        unsigned b = (unsigned)(v.x >= uthr) | ((unsigned)(v.y >= uthr) << 1)
                   | ((unsigned)(v.z >= uthr) << 2) | ((unsigned)(v.w >= uthr) << 3);
        if (j < 8) m0 |= b << (4 * j); else m1 |= b << (4 * (j - 8));
    }
    __syncwarp();                                  // counter reset visible
    __ballot_sync(0xffffffffu, (m0 | m1) != 0u);   // reconverge; >=1 lane has the max
    if (m0 | m1) {
#pragma unroll
        for (int j = 0; j < 16; j++) {
            unsigned b = (j < 8) ? (m0 >> (4 * j)) & 0xFu : (m1 >> (4 * (j - 8))) & 0xFu;
            if (b) {
                const int kb = (j * 32 + lane) * 4;
                const float4 v = ur[j];
                if (b & 1u) { int q = atomicAdd(s_cnt, 1); if (q < CAP) { kl[q] = kb + 0; ul[q] = v.x; } }
                if (b & 2u) { int q = atomicAdd(s_cnt, 1); if (q < CAP) { kl[q] = kb + 1; ul[q] = v.y; } }
                if (b & 4u) { int q = atomicAdd(s_cnt, 1); if (q < CAP) { kl[q] = kb + 2; ul[q] = v.z; } }
                if (b & 8u) { int q = atomicAdd(s_cnt, 1); if (q < CAP) { kl[q] = kb + 3; ul[q] = v.w; } }
            }
        }
    }
    __syncwarp();
    int cnt = *s_cnt;
    return cnt > CAP ? CAP : cnt;
}

// Score candidates: fast fp32 path (single butterfly via |z-c|^2, 2-wide ILP),
// fp64-faithful refinement on near-ties (margin 1e-2 >> combined fp noise).
__device__ __forceinline__ int score_pick(
    float4 z, float x2, float t, const float* __restrict__ cbm,
    int cnt, const int* kl, const float* ul, int lane)
{
    const float EPSF = 1e-6f, HI = (float)(1.0 - 1e-6);
    if (cnt <= 1) return kl[0];            // umax always qualifies -> cnt >= 1

    float best_s = -3.4e38f, sec_s = -3.4e38f;
    int   best_k = 0;
    for (int base = 0; base < cnt; base += 2) {
        float dd[2]; int kk[2];
#pragma unroll
        for (int i2 = 0; i2 < 2; i2++) {
            int i = base + i2; if (i > cnt - 1) i = cnt - 1;
            int k = kl[i]; kk[i2] = k;
            float4 c = reinterpret_cast<const float4*>(cbm)[(size_t)k * (DQ / 4) + lane];
            float ex = z.x - c.x, ey = z.y - c.y, ez = z.z - c.z, ew = z.w - c.w;
            dd[i2] = ex * ex + ey * ey + ez * ez + ew * ew;
        }
#pragma unroll
        for (int o = 16; o; o >>= 1) {
            dd[0] += __shfl_xor_sync(0xffffffffu, dd[0], o);
            dd[1] += __shfl_xor_sync(0xffffffffu, dd[1], o);
        }
#pragma unroll
        for (int i2 = 0; i2 < 2; i2++) {
            int i = base + i2; if (i >= cnt) break;
            float uc = fminf(fmaxf(ul[i], EPSF), HI);
            float g  = -logf(-logf(uc));
            float sc = -dd[i2] / c_SCALE * t + g;
            int   k  = kk[i2];
            if (sc > best_s || (sc == best_s && k < best_k)) {
                sec_s = best_s; best_s = sc; best_k = k;
            } else if (sc > sec_s) sec_s = sc;
        }
    }

    if (best_s - sec_s < 1e-2f) {          // rare: reference-faithful rescore
        best_s = -3.4e38f; best_k = 0;
        for (int i = 0; i < cnt; i++) {
            const int k = kl[i];
            float4 c = reinterpret_cast<const float4*>(cbm)[(size_t)k * (DQ / 4) + lane];
            float p = warp_sum(z.x * c.x + z.y * c.y + z.z * c.z + z.w * c.w);
            float q = warp_sum(c.x * c.x + c.y * c.y + c.z * c.z + c.w * c.w);
            double ucl = (double)fminf(fmaxf(ul[i], EPSF), HI);
            float  g   = (float)(-log(-log(ucl)));
            float dist  = __fadd_rn(__fadd_rn(x2, q), -__fmul_rn(2.0f, p));
            float logit = __fmul_rn(__fdiv_rn(-dist, c_SCALE), t);
            float sc    = __fadd_rn(logit, g);
            if (sc > best_s || (sc == best_s && k < best_k)) { best_s = sc; best_k = k; }
        }
    }
    __syncwarp();
    return best_k;
}

__global__ void __launch_bounds__(256) umgm_kernel(
    const float* __restrict__ x,
    const float* __restrict__ cb0,
    const float* __restrict__ cb1,
    const float* __restrict__ t0p,
    const float* __restrict__ t1p,
    const float* __restrict__ u0,
    const float* __restrict__ u1,
    float* __restrict__ out)
{
    __shared__ int   s_cnt[8];
    __shared__ int   s_k[8][CAP];
    __shared__ float s_u[8][CAP];
    const int w    = threadIdx.x >> 5;
    const int lane = threadIdx.x & 31;
    const int row  = blockIdx.x * 8 + w;   // row = n*M + m (matches u layout)
    const int n    = row >> 3;
    const int m    = row & 7;
    const float EPSF = 1e-6f;

    const float4* u0row = reinterpret_cast<const float4*>(u0) + (size_t)row * (KQ / 4);
    const float4* u1row = reinterpret_cast<const float4*>(u1) + (size_t)row * (KQ / 4);

    float4 z = reinterpret_cast<const float4*>(x + (size_t)n * CH + m * DQ)[lane];
    float x2 = warp_sum(z.x * z.x + z.y * z.y + z.z * z.z + z.w * z.w);

    const float* cbm0 = cb0 + (size_t)m * KQ * DQ;
    const float* cbm1 = cb1 + (size_t)m * KQ * DQ;
    const float t0 = fmaxf(t0p[m], EPSF);
    const float t1 = fmaxf(t1p[m], EPSF);

    // ---- level-0 burst: pure load + fmax (nothing else in the loop) ----
    float4 ur[16];
    float umax0 = 0.0f;
#pragma unroll
    for (int j = 0; j < 16; j++) {
        ur[j] = u0row[j * 32 + lane];
        umax0 = fmaxf(umax0, fmaxf(fmaxf(ur[j].x, ur[j].y), fmaxf(ur[j].z, ur[j].w)));
    }
    umax0 = warp_max_pos(umax0);

    float uthr0 = make_uthr(umax0, t0, x2, __uint_as_float(g_cm2[0][m]));
    int  cnt0   = build_push(ur, uthr0, lane, &s_cnt[w], s_k[w], s_u[w]);

    // ---- level-1 burst NOW (ur dead): its DRAM fetch overlaps level-0 scoring ----
    float umax1 = 0.0f;
#pragma unroll
    for (int j = 0; j < 16; j++) {
        ur[j] = u1row[j * 32 + lane];
        umax1 = fmaxf(umax1, fmaxf(fmaxf(ur[j].x, ur[j].y), fmaxf(ur[j].z, ur[j].w)));
    }

    // ---- level-0 scoring (burst-1 in flight) ----
    int k0 = score_pick(z, x2, t0, cbm0, cnt0, s_k[w], s_u[w], lane);
    float4 c0 = reinterpret_cast<const float4*>(cbm0)[(size_t)k0 * (DQ / 4) + lane];
    float4 z1 = make_float4(z.x - c0.x, z.y - c0.y, z.z - c0.z, z.w - c0.w);
    float x2b = warp_sum(z1.x * z1.x + z1.y * z1.y + z1.z * z1.z + z1.w * z1.w);

    // ---- level-1 processing ----
    umax1 = warp_max_pos(umax1);
    float uthr1 = make_uthr(umax1, t1, x2b, __uint_as_float(g_cm2[1][m]));
    int  cnt1   = build_push(ur, uthr1, lane, &s_cnt[w], s_k[w], s_u[w]);
    int  k1     = score_pick(z1, x2b, t1, cbm1, cnt1, s_k[w], s_u[w], lane);
    float4 c1 = reinterpret_cast<const float4*>(cbm1)[(size_t)k1 * (DQ / 4) + lane];

    float4 o = make_float4(c0.x + c1.x, c0.y + c1.y, c0.z + c1.z, c0.w + c1.w);
    reinterpret_cast<float4*>(out + (size_t)n * CH + m * DQ)[lane] = o;
}

extern "C" void kernel_launch(void* const* d_in, const int* in_sizes, int n_in,
                              void* d_out, int out_size) {
    const float *x = nullptr, *cb0 = nullptr, *cb1 = nullptr,
                *t0 = nullptr, *t1 = nullptr, *u0 = nullptr, *u1 = nullptr;
    for (int i = 0; i < n_in; i++) {
        const float* p = (const float*)d_in[i];
        const long sz = in_sizes[i];
        if      (sz == (long)NROW * CH)        { x = p; }
        else if (sz == (long)MQ * KQ * DQ)     { if (!cb0) cb0 = p; else cb1 = p; }
        else if (sz == (long)MQ)               { if (!t0)  t0  = p; else t1  = p; }
        else if (sz == (long)NROW * MQ * KQ)   { if (!u0)  u0  = p; else u1  = p; }
    }
    float* out = (float*)d_out;
    (void)out_size;

    dim3 gc((MQ * KQ) / (4 * 8), 2);       // warp handles 4 k's, 8 warps/block
    cm2_k<<<gc, 256>>>(cb0, cb1);
    umgm_kernel<<<(NROW * MQ) / 8, 256>>>(x, cb0, cb1, t0, t1, u0, u1, out);
}

// round 10
// speedup vs baseline: 1.7668x; 1.0593x over previous
#include <cuda_runtime.h>
#include <math.h>
#include <stdint.h>

#define NROW 4096
#define CH   1024
#define MQ   8
#define KQ   2048
#define DQ   128
#define CAP  64

// Scratch: level-0 picks (k0 per row) + per-(level,m) max|c|^2 (ordered uint).
// Zero-init at load; cm2 atomicMax idempotent across graph replays; g_k0 is
// rewritten identically every replay.
static __device__ int      g_k0[NROW * MQ];
static __device__ unsigned g_cm2[2][MQ];

// One warp per 4 consecutive k: 4 interleaved butterflies, one atomicMax.
__global__ void cm2_k(const float* __restrict__ cb0, const float* __restrict__ cb1) {
    const int level = blockIdx.y;
    const float* cb = level ? cb1 : cb0;
    const int w    = (blockIdx.x * blockDim.x + threadIdx.x) >> 5;
    const int lane = threadIdx.x & 31;
    if (w >= (MQ * KQ) / 4) return;
    float s[4];
#pragma unroll
    for (int r = 0; r < 4; r++) {
        float4 v = reinterpret_cast<const float4*>(cb)[(size_t)(w * 4 + r) * (DQ / 4) + lane];
        s[r] = v.x * v.x + v.y * v.y + v.z * v.z + v.w * v.w;
    }
#pragma unroll
    for (int o = 16; o; o >>= 1)
#pragma unroll
        for (int r = 0; r < 4; r++) s[r] += __shfl_xor_sync(0xffffffffu, s[r], o);
    if (lane == 0) {
        float mx = fmaxf(fmaxf(s[0], s[1]), fmaxf(s[2], s[3]));
        atomicMax(&g_cm2[level][(w * 4) >> 11], __float_as_uint(mx));
    }
}

__device__ __forceinline__ float warp_sum(float v) {
#pragma unroll
    for (int o = 16; o; o >>= 1) v += __shfl_xor_sync(0xffffffffu, v, o);
    return v;
}
__device__ __forceinline__ float warp_max_pos(float v) {   // non-negative floats
    unsigned r;
    asm("redux.sync.max.u32 %0, %1, 0xffffffff;" : "=r"(r) : "r"(__float_as_uint(v)));
    return __uint_as_float(r);
}

__constant__ float c_SCALE = 45.25483399593904f;   // sqrt(2048)

// Threshold: g(u) = -log(-log u) monotone in u; candidate iff u >= uthr.
// delta = Cauchy-Schwarz logit-spread bound, inflated for fp noise.
__device__ __forceinline__ float make_uthr(float umax, float t, float x2, float cm2) {
    const float EPSF = 1e-6f, HI = (float)(1.0 - 1e-6);
    const float cmax = sqrtf(cm2);
    float delta = (t / c_SCALE) * (4.0f * sqrtf(x2) * cmax + cm2);
    delta = delta * 1.01f + 0.02f;
    float ucm  = fminf(fmaxf(umax, EPSF), HI);
    float gm   = -logf(-logf(ucm));
    float uthr = expf(-expf(-(gm - delta))) * (1.0f - 1e-5f);
    return fminf(uthr, umax);                 // max element always qualifies
}

// Inline pass-2: single-ballot mask filter over register-resident ur.
#define PASS2_PUSH(ur, uthr, lane, pcnt, kl, ul)                                          \
    {                                                                                      \
        if ((lane) == 0) *(pcnt) = 0;                                                      \
        unsigned m0_ = 0u, m1_ = 0u;                                                       \
        _Pragma("unroll")                                                                  \
        for (int j = 0; j < 16; j++) {                                                     \
            const float4 v = (ur)[j];                                                      \
            unsigned b = (unsigned)(v.x >= (uthr)) | ((unsigned)(v.y >= (uthr)) << 1)      \
                       | ((unsigned)(v.z >= (uthr)) << 2) | ((unsigned)(v.w >= (uthr)) << 3);\
            if (j < 8) m0_ |= b << (4 * j); else m1_ |= b << (4 * (j - 8));                \
        }                                                                                  \
        __syncwarp();                                                                      \
        __ballot_sync(0xffffffffu, (m0_ | m1_) != 0u);                                     \
        if (m0_ | m1_) {                                                                   \
            _Pragma("unroll")                                                              \
            for (int j = 0; j < 16; j++) {                                                 \
                unsigned b = (j < 8) ? (m0_ >> (4 * j)) & 0xFu : (m1_ >> (4 * (j - 8))) & 0xFu; \
                if (b) {                                                                   \
                    const int kb = (j * 32 + (lane)) * 4;                                  \
                    const float4 v = (ur)[j];                                              \
                    if (b & 1u) { int q = atomicAdd((pcnt), 1); if (q < CAP) { (kl)[q] = kb + 0; (ul)[q] = v.x; } } \
                    if (b & 2u) { int q = atomicAdd((pcnt), 1); if (q < CAP) { (kl)[q] = kb + 1; (ul)[q] = v.y; } } \
                    if (b & 4u) { int q = atomicAdd((pcnt), 1); if (q < CAP) { (kl)[q] = kb + 2; (ul)[q] = v.z; } } \
                    if (b & 8u) { int q = atomicAdd((pcnt), 1); if (q < CAP) { (kl)[q] = kb + 3; (ul)[q] = v.w; } } \
                }                                                                          \
            }                                                                              \
        }                                                                                  \
        __syncwarp();                                                                      \
    }

// Score candidates: fast fp32 (|z-c|^2 single butterfly, 2-wide ILP) + rare
// fp64-faithful refinement on near-ties (margin 1e-2 >> combined fp noise).
__device__ __forceinline__ int score_pick(
    float4 z, float x2, float t, const float* __restrict__ cbm,
    int cnt, const int* kl, const float* ul, int lane)
{
    const float EPSF = 1e-6f, HI = (float)(1.0 - 1e-6);
    if (cnt <= 1) return kl[0];            // umax always qualifies -> cnt >= 1

    float best_s = -3.4e38f, sec_s = -3.4e38f;
    int   best_k = 0;
    for (int base = 0; base < cnt; base += 2) {
        float dd[2]; int kk[2];
#pragma unroll
        for (int i2 = 0; i2 < 2; i2++) {
            int i = base + i2; if (i > cnt - 1) i = cnt - 1;
            int k = kl[i]; kk[i2] = k;
            float4 c = reinterpret_cast<const float4*>(cbm)[(size_t)k * (DQ / 4) + lane];
            float ex = z.x - c.x, ey = z.y - c.y, ez = z.z - c.z, ew = z.w - c.w;
            dd[i2] = ex * ex + ey * ey + ez * ez + ew * ew;
        }
#pragma unroll
        for (int o = 16; o; o >>= 1) {
            dd[0] += __shfl_xor_sync(0xffffffffu, dd[0], o);
            dd[1] += __shfl_xor_sync(0xffffffffu, dd[1], o);
        }
#pragma unroll
        for (int i2 = 0; i2 < 2; i2++) {
            int i = base + i2; if (i >= cnt) break;
            float uc = fminf(fmaxf(ul[i], EPSF), HI);
            float g  = -logf(-logf(uc));
            float sc = -dd[i2] / c_SCALE * t + g;
            int   k  = kk[i2];
            if (sc > best_s || (sc == best_s && k < best_k)) {
                sec_s = best_s; best_s = sc; best_k = k;
            } else if (sc > sec_s) sec_s = sc;
        }
    }

    if (best_s - sec_s < 1e-2f) {          // rare: reference-faithful rescore
        best_s = -3.4e38f; best_k = 0;
        for (int i = 0; i < cnt; i++) {
            const int k = kl[i];
            float4 c = reinterpret_cast<const float4*>(cbm)[(size_t)k * (DQ / 4) + lane];
            float p = warp_sum(z.x * c.x + z.y * c.y + z.z * c.z + z.w * c.w);
            float q = warp_sum(c.x * c.x + c.y * c.y + c.z * c.z + c.w * c.w);
            double ucl = (double)fminf(fmaxf(ul[i], EPSF), HI);
            float  g   = (float)(-log(-log(ucl)));
            float dist  = __fadd_rn(__fadd_rn(x2, q), -__fmul_rn(2.0f, p));
            float logit = __fmul_rn(__fdiv_rn(-dist, c_SCALE), t);
            float sc    = __fadd_rn(logit, g);
            if (sc > best_s || (sc == best_s && k < best_k)) { best_s = sc; best_k = k; }
        }
    }
    __syncwarp();
    return best_k;
}

// ---- Kernel A: level 0 -> g_k0[row] ----
__global__ void __launch_bounds__(256, 3) level0_k(
    const float* __restrict__ x,
    const float* __restrict__ cb0,
    const float* __restrict__ t0p,
    const float* __restrict__ u0)
{
    __shared__ int   s_cnt[8];
    __shared__ int   s_k[8][CAP];
    __shared__ float s_u[8][CAP];
    const int w    = threadIdx.x >> 5;
    const int lane = threadIdx.x & 31;
    const int row  = blockIdx.x * 8 + w;   // row = n*M + m
    const int n    = row >> 3;
    const int m    = row & 7;

    const float4* u0row = reinterpret_cast<const float4*>(u0) + (size_t)row * (KQ / 4);

    // Burst FIRST: 16 front-batched LDG.128/lane (nothing else in the loop).
    float4 ur[16];
    float umax = 0.0f;
#pragma unroll
    for (int j = 0; j < 16; j++) {
        ur[j] = u0row[j * 32 + lane];
        umax = fmaxf(umax, fmaxf(fmaxf(ur[j].x, ur[j].y), fmaxf(ur[j].z, ur[j].w)));
    }

    // These loads + butterfly execute under the burst's latency.
    float4 z = reinterpret_cast<const float4*>(x + (size_t)n * CH + m * DQ)[lane];
    const float t0 = fmaxf(t0p[m], 1e-6f);
    const float cm2 = __uint_as_float(g_cm2[0][m]);
    float x2 = warp_sum(z.x * z.x + z.y * z.y + z.z * z.z + z.w * z.w);

    umax = warp_max_pos(umax);
    float uthr = make_uthr(umax, t0, x2, cm2);
    PASS2_PUSH(ur, uthr, lane, &s_cnt[w], s_k[w], s_u[w]);
    int cnt = s_cnt[w]; if (cnt > CAP) cnt = CAP;

    const float* cbm0 = cb0 + (size_t)m * KQ * DQ;
    int k0 = score_pick(z, x2, t0, cbm0, cnt, s_k[w], s_u[w], lane);
    if (lane == 0) g_k0[row] = k0;
}

// ---- Kernel B: level 1 + output ----
__global__ void __launch_bounds__(256, 3) level1_k(
    const float* __restrict__ x,
    const float* __restrict__ cb0,
    const float* __restrict__ cb1,
    const float* __restrict__ t1p,
    const float* __restrict__ u1,
    float* __restrict__ out)
{
    __shared__ int   s_cnt[8];
    __shared__ int   s_k[8][CAP];
    __shared__ float s_u[8][CAP];
    const int w    = threadIdx.x >> 5;
    const int lane = threadIdx.x & 31;
    const int row  = blockIdx.x * 8 + w;
    const int n    = row >> 3;
    const int m    = row & 7;

    const float4* u1row = reinterpret_cast<const float4*>(u1) + (size_t)row * (KQ / 4);

    // Burst FIRST.
    float4 ur[16];
    float umax = 0.0f;
#pragma unroll
    for (int j = 0; j < 16; j++) {
        ur[j] = u1row[j * 32 + lane];
        umax = fmaxf(umax, fmaxf(fmaxf(ur[j].x, ur[j].y), fmaxf(ur[j].z, ur[j].w)));
    }

    // Residual construction under burst latency.
    float4 z = reinterpret_cast<const float4*>(x + (size_t)n * CH + m * DQ)[lane];
    const int   k0  = g_k0[row];
    const float t1  = fmaxf(t1p[m], 1e-6f);
    const float cm2 = __uint_as_float(g_cm2[1][m]);
    const float* cbm0 = cb0 + (size_t)m * KQ * DQ;
    const float* cbm1 = cb1 + (size_t)m * KQ * DQ;
    float4 c0 = reinterpret_cast<const float4*>(cbm0)[(size_t)k0 * (DQ / 4) + lane];
    float4 z1 = make_float4(z.x - c0.x, z.y - c0.y, z.z - c0.z, z.w - c0.w);
    float x2b = warp_sum(z1.x * z1.x + z1.y * z1.y + z1.z * z1.z + z1.w * z1.w);

    umax = warp_max_pos(umax);
    float uthr = make_uthr(umax, t1, x2b, cm2);
    PASS2_PUSH(ur, uthr, lane, &s_cnt[w], s_k[w], s_u[w]);
    int cnt = s_cnt[w]; if (cnt > CAP) cnt = CAP;

    int k1 = score_pick(z1, x2b, t1, cbm1, cnt, s_k[w], s_u[w], lane);
    float4 c1 = reinterpret_cast<const float4*>(cbm1)[(size_t)k1 * (DQ / 4) + lane];

    float4 o = make_float4(c0.x + c1.x, c0.y + c1.y, c0.z + c1.z, c0.w + c1.w);
    reinterpret_cast<float4*>(out + (size_t)n * CH + m * DQ)[lane] = o;
}

extern "C" void kernel_launch(void* const* d_in, const int* in_sizes, int n_in,
                              void* d_out, int out_size) {
    const float *x = nullptr, *cb0 = nullptr, *cb1 = nullptr,
                *t0 = nullptr, *t1 = nullptr, *u0 = nullptr, *u1 = nullptr;
    for (int i = 0; i < n_in; i++) {
        const float* p = (const float*)d_in[i];
        const long sz = in_sizes[i];
        if      (sz == (long)NROW * CH)        { x = p; }
        else if (sz == (long)MQ * KQ * DQ)     { if (!cb0) cb0 = p; else cb1 = p; }
        else if (sz == (long)MQ)               { if (!t0)  t0  = p; else t1  = p; }
        else if (sz == (long)NROW * MQ * KQ)   { if (!u0)  u0  = p; else u1  = p; }
    }
    float* out = (float*)d_out;
    (void)out_size;

    dim3 gc((MQ * KQ) / (4 * 8), 2);
    cm2_k<<<gc, 256>>>(cb0, cb1);
    level0_k<<<(NROW * MQ) / 8, 256>>>(x, cb0, t0, u0);
    level1_k<<<(NROW * MQ) / 8, 256>>>(x, cb0, cb1, t1, u1, out);
}